// round 12
// baseline (speedup 1.0000x reference)
#include <cuda_runtime.h>
#include <cuda_fp16.h>
#include <cstdint>

// Problem constants (fixed by the reference)
#define BATCH   50000
#define KNEI    32
#define FDIM    256     // feature dim; 2F = 512 = GEMM K
#define NNODES  200000
#define NOUT    256

// fp16 copy of the feature table [NNODES, FDIM] (rebuilt every call)
__device__ __half g_feats_h[(size_t)NNODES * FDIM];
// fp16 concatenated GEMM A matrix: [BATCH][512] = [x_self_f16 | x_neigh_f16]
__device__ __half g_h[(size_t)BATCH * 2 * FDIM];
// fp16 transposed weights: W_t[n][k], n in [0,256), k in [0,512)
__device__ __half g_W_t[(size_t)NOUT * 2 * FDIM];

#define FEATS_BLOCKS ((NNODES * FDIM) / (256 * 8))   // 25000
#define XSELF_BLOCKS ((BATCH * FDIM) / (256 * 8))    // 6250
#define W_BLOCKS     ((2 * FDIM / 32) * (NOUT / 32)) // 128
#define NGATHER      (BATCH / 8)                     // 6250

// ---------------------------------------------------------------------------
// Kernel 1: fp32 -> fp16: feats table + W transpose.  HBM streaming.
// (x_self conversion moved into the gather kernel's grid — no dependency.)
// ---------------------------------------------------------------------------
__global__ void convert_kernel(const float4* __restrict__ feats4,
                               const float* __restrict__ W) {
    const int bid = blockIdx.x;
    if (bid < FEATS_BLOCKS) {
        const long long t = (long long)bid * 256 + threadIdx.x;
        const float4 a = feats4[2 * t];
        const float4 b = feats4[2 * t + 1];
        __half2 o[4];
        o[0] = __floats2half2_rn(a.x, a.y);
        o[1] = __floats2half2_rn(a.z, a.w);
        o[2] = __floats2half2_rn(b.x, b.y);
        o[3] = __floats2half2_rn(b.z, b.w);
        *reinterpret_cast<uint4*>(g_feats_h + t * 8) = *reinterpret_cast<uint4*>(o);
    } else {
        // W transpose: 32x32 fp32 tile -> fp16 W_t
        __shared__ float tile[32][33];
        const int b2 = bid - FEATS_BLOCKS;
        const int k0 = (b2 & 15) * 32;      // 16 k-blocks
        const int n0 = (b2 >> 4) * 32;      // 8 n-blocks
        const int tx = threadIdx.x & 31;
        const int ty = threadIdx.x >> 5;    // 0..7
#pragma unroll
        for (int j = 0; j < 4; j++)
            tile[ty + j * 8][tx] = W[(long long)(k0 + ty + j * 8) * NOUT + n0 + tx];
        __syncthreads();
#pragma unroll
        for (int j = 0; j < 4; j++) {
            const int n = ty + j * 8;
            g_W_t[(long long)(n0 + n) * (2 * FDIM) + k0 + tx] =
                __float2half(tile[tx][n]);
        }
    }
}

// ---------------------------------------------------------------------------
// Kernel 2 (heterogeneous): even bids gather+mean (L2-bound), odd bids
// convert x_self fp32 -> fp16 (HBM-bound) — the two overlap.
// Gather: 8 rows/block, 1 warp per row, fp32 accumulate, fp16 out into
// g_h cols [256,512).  Index dtype detected per-block (int64 hi words == 0).
// ---------------------------------------------------------------------------
__global__ void gather_xself_kernel(const void* __restrict__ idx_raw,
                                    const float4* __restrict__ xself4) {
    const int tid = threadIdx.x;

    if (blockIdx.x & 1) {
        // ---- x_self convert block ----
        const long long e = (long long)(blockIdx.x >> 1) * 256 + tid;
        const float4 a = xself4[2 * e];
        const float4 b = xself4[2 * e + 1];
        __half2 o[4];
        o[0] = __floats2half2_rn(a.x, a.y);
        o[1] = __floats2half2_rn(a.z, a.w);
        o[2] = __floats2half2_rn(b.x, b.y);
        o[3] = __floats2half2_rn(b.z, b.w);
        const long long row = e / 32;          // 32 * 8 halves = 256 per row
        const long long col = (e % 32) * 8;
        *reinterpret_cast<uint4*>(g_h + row * (2 * FDIM) + col) =
            *reinterpret_cast<uint4*>(o);
        return;
    }

    // ---- gather block ----
    const int gblk = blockIdx.x >> 1;
    const int warp = tid >> 5;
    const int lane = tid & 31;

    int hi_zero = 1;
    if (tid < 128) {
        const uint2 probe = reinterpret_cast<const uint2*>(idx_raw)[tid];
        hi_zero = (probe.y == 0u);
    }
    const int is64 = __syncthreads_and(hi_zero);

    __shared__ int sidx[256];
    const long long flat = (long long)gblk * 256 + tid;
    int v;
    if (is64) v = (int)reinterpret_cast<const long long*>(idx_raw)[flat];
    else      v = reinterpret_cast<const int*>(idx_raw)[flat];
    sidx[tid] = v;
    __syncthreads();

    const int row = gblk * 8 + warp;

    float acc[8];
#pragma unroll
    for (int j = 0; j < 8; j++) acc[j] = 0.f;

#pragma unroll
    for (int k = 0; k < KNEI; k++) {
        const long long node = sidx[warp * KNEI + k];
        const uint4 raw = *reinterpret_cast<const uint4*>(
            g_feats_h + node * FDIM + lane * 8);
        const __half2* h = reinterpret_cast<const __half2*>(&raw);
#pragma unroll
        for (int j = 0; j < 4; j++) {
            const float2 f = __half22float2(h[j]);
            acc[2 * j]     += f.x;
            acc[2 * j + 1] += f.y;
        }
    }
    const float s = 1.0f / (float)KNEI;
    __half2 o[4];
#pragma unroll
    for (int j = 0; j < 4; j++)
        o[j] = __floats2half2_rn(acc[2 * j] * s, acc[2 * j + 1] * s);
    *reinterpret_cast<uint4*>(g_h + (long long)row * (2 * FDIM) + FDIM + lane * 8) =
        *reinterpret_cast<uint4*>(o);
}

// ---------------------------------------------------------------------------
// Kernel 3: fp16 tensor-core GEMM, 4-stage cp.async pipeline (round-7 proven
// config, 46.8us).  out[M,256] = g_h[M,512] @ W_t^T + bias
// BM=128, BN=64, BK=32, STAGES=4 (48KB smem, 4 CTAs/SM).  8 warps:
// 4 in M x 2 in N, warp tile 32x32 -> 32 fp32 accs/thread (regs <= 64).
// Grid: x = n-tile (4), y = m-tile (391) so the 4 CTAs sharing an A tile are
// consecutive bids -> A re-reads hit L2 while hot.
// ---------------------------------------------------------------------------
#define BM 128
#define BN 64
#define BK 32
#define STAGES 4
#define A_TILE_B (BM * BK * 2)            // 8192
#define B_TILE_B (BN * BK * 2)            // 4096
#define STAGE_B  (A_TILE_B + B_TILE_B)    // 12288

__device__ __forceinline__ unsigned swz(unsigned off) {
    return off ^ (((off >> 7) & 7u) << 4);
}

__device__ __forceinline__ void mma_f16(float& d0, float& d1, float& d2, float& d3,
                                        unsigned a0, unsigned a1, unsigned a2, unsigned a3,
                                        unsigned b0, unsigned b1) {
    asm volatile(
        "mma.sync.aligned.m16n8k16.row.col.f32.f16.f16.f32 "
        "{%0,%1,%2,%3}, {%4,%5,%6,%7}, {%8,%9}, {%0,%1,%2,%3};"
        : "+f"(d0), "+f"(d1), "+f"(d2), "+f"(d3)
        : "r"(a0), "r"(a1), "r"(a2), "r"(a3), "r"(b0), "r"(b1));
}

__device__ __forceinline__ void ldmatrix_x4(unsigned& r0, unsigned& r1,
                                            unsigned& r2, unsigned& r3,
                                            unsigned saddr) {
    asm volatile("ldmatrix.sync.aligned.m8n8.x4.shared.b16 {%0,%1,%2,%3}, [%4];"
                 : "=r"(r0), "=r"(r1), "=r"(r2), "=r"(r3) : "r"(saddr));
}

__device__ __forceinline__ void cp_async16(unsigned dst, const void* src, int sz) {
    asm volatile("cp.async.cg.shared.global [%0], [%1], 16, %2;\n"
                 :: "r"(dst), "l"(src), "r"(sz));
}
__device__ __forceinline__ void cp_commit() {
    asm volatile("cp.async.commit_group;\n");
}
template <int N>
__device__ __forceinline__ void cp_wait() {
    asm volatile("cp.async.wait_group %0;\n" :: "n"(N));
}

__global__ __launch_bounds__(256, 4)
void gemm_f16_pipe_kernel(const float* __restrict__ bias,
                          float* __restrict__ out,
                          int M) {
    __shared__ __align__(16) char smem[STAGES * STAGE_B];   // 48 KB

    const int bm  = blockIdx.y * BM;
    const int bn  = blockIdx.x * BN;
    const int tid = threadIdx.x;

    const int warp = tid >> 5;
    const int lane = tid & 31;
    const int wm   = warp >> 1;        // 0..3
    const int wn   = warp & 1;         // 0..1
    const int gid  = lane >> 2;        // 0..7
    const int tig  = lane & 3;         // 0..3

    const unsigned sbase = (unsigned)__cvta_generic_to_shared(smem);

    const __half* __restrict__ A  = g_h;
    const __half* __restrict__ Wt = g_W_t;

    // A fragment ldmatrix lane addressing
    const int lm_tile = lane >> 3;
    const int lm_row  = (lane & 7) + (lm_tile & 1) * 8;
    const int lm_koff = (lm_tile >> 1) * 8;
    // B fragment ldmatrix lane addressing (non-trans over [n][k] rows)
    const int bn_row  = ((lane >> 4) & 1) * 8 + (lane & 7);
    const int bk_add  = ((lane >> 3) & 1) * 8;

    float acc[2][4][4];
#pragma unroll
    for (int i = 0; i < 2; i++)
#pragma unroll
        for (int j = 0; j < 4; j++)
#pragma unroll
            for (int q = 0; q < 4; q++) acc[i][j][q] = 0.f;

    // stage s covers k0 = s*BK halves.  Per stage: A = 512 16B-granules
    // (2/thread), B = 256 granules (1/thread).
#define ISSUE_STAGE(s, buf)                                                     \
    {                                                                           \
        const int k0 = (s) * BK;                                                \
        const unsigned abase = sbase + (buf) * STAGE_B;                         \
        const unsigned bbase = abase + A_TILE_B;                                \
        _Pragma("unroll")                                                       \
        for (int i = 0; i < 2; i++) {                                           \
            const int fi = tid + i * 256;                                       \
            const int r  = fi >> 2;                                             \
            const int g  = fi & 3;                                              \
            const unsigned soff = swz((unsigned)(r * 64 + g * 16));             \
            const int m = bm + r;                                               \
            cp_async16(abase + soff,                                            \
                       A + (long long)m * (2 * FDIM) + k0 + g * 8,              \
                       (m < M) ? 16 : 0);                                       \
        }                                                                       \
        {                                                                       \
            const int r = tid >> 2;                                             \
            const int g = tid & 3;                                              \
            const unsigned soff = swz((unsigned)(r * 64 + g * 16));             \
            cp_async16(bbase + soff,                                            \
                       Wt + (long long)(bn + r) * (2 * FDIM) + k0 + g * 8, 16); \
        }                                                                       \
        cp_commit();                                                            \
    }

    // ---- prologue: issue stages 0,1,2 ----
    ISSUE_STAGE(0, 0)
    ISSUE_STAGE(1, 1)
    ISSUE_STAGE(2, 2)

    const int NSTAGE = (2 * FDIM) / BK;   // 16

#pragma unroll 1
    for (int s = 0; s < NSTAGE; s++) {
        if (s < NSTAGE - 2)       cp_wait<2>();
        else if (s == NSTAGE - 2) cp_wait<1>();
        else                      cp_wait<0>();
        __syncthreads();

        // issue stage s+3 into buffer (s+3)%4
        if (s + 3 < NSTAGE) {
            const int nb = (s + 3) % STAGES;
            ISSUE_STAGE(s + 3, nb)
        }

        // compute stage s from buffer s%4
        const unsigned abase = sbase + (s % STAGES) * STAGE_B;
        const unsigned bbase = abase + A_TILE_B;

#pragma unroll
        for (int ks = 0; ks < 2; ks++) {
            const int kk = ks * 16;
            unsigned af[2][4];
#pragma unroll
            for (int mi = 0; mi < 2; mi++) {
                const int r = wm * 32 + mi * 16 + lm_row;
                const unsigned sa = abase + swz((unsigned)(r * 64 + (kk + lm_koff) * 2));
                ldmatrix_x4(af[mi][0], af[mi][1], af[mi][2], af[mi][3], sa);
            }
            unsigned bf[4][2];
#pragma unroll
            for (int nj2 = 0; nj2 < 2; nj2++) {
                const int n = wn * 32 + nj2 * 16 + bn_row;
                const unsigned sb = bbase + swz((unsigned)(n * 64 + (kk + bk_add) * 2));
                unsigned r0, r1, r2, r3;
                ldmatrix_x4(r0, r1, r2, r3, sb);
                bf[2 * nj2][0]     = r0; bf[2 * nj2][1]     = r1;
                bf[2 * nj2 + 1][0] = r2; bf[2 * nj2 + 1][1] = r3;
            }
#pragma unroll
            for (int nj = 0; nj < 4; nj++) {
                mma_f16(acc[0][nj][0], acc[0][nj][1], acc[0][nj][2], acc[0][nj][3],
                        af[0][0], af[0][1], af[0][2], af[0][3], bf[nj][0], bf[nj][1]);
                mma_f16(acc[1][nj][0], acc[1][nj][1], acc[1][nj][2], acc[1][nj][3],
                        af[1][0], af[1][1], af[1][2], af[1][3], bf[nj][0], bf[nj][1]);
            }
        }
        __syncthreads();
    }

    // ---- epilogue: bias + store (c0,c1 contiguous -> float2) ----
#pragma unroll
    for (int mi = 0; mi < 2; mi++) {
        const int m0 = bm + wm * 32 + mi * 16 + gid;
#pragma unroll
        for (int nj = 0; nj < 4; nj++) {
            const int n = bn + wn * 32 + nj * 8 + 2 * tig;
            const float b0 = bias[n];
            const float b1 = bias[n + 1];
            if (m0 < M) {
                float2 v = make_float2(acc[mi][nj][0] + b0, acc[mi][nj][1] + b1);
                *reinterpret_cast<float2*>(out + (long long)m0 * NOUT + n) = v;
            }
            if (m0 + 8 < M) {
                float2 v = make_float2(acc[mi][nj][2] + b0, acc[mi][nj][3] + b1);
                *reinterpret_cast<float2*>(out + (long long)(m0 + 8) * NOUT + n) = v;
            }
        }
    }
#undef ISSUE_STAGE
}

// ---------------------------------------------------------------------------
// Launch
// Inputs: x_self[f32 B*F], feats[f32 N*F], neigh_idx[B*K], W[f32 512*256], b[f32 256]
// ---------------------------------------------------------------------------
extern "C" void kernel_launch(void* const* d_in, const int* in_sizes, int n_in,
                              void* d_out, int out_size) {
    const float4* xself4 = (const float4*)d_in[0];
    const float4* feats4 = (const float4*)d_in[1];
    const void*   nidx   = d_in[2];
    const float*  W      = (const float*)d_in[3];
    const float*  bias   = (const float*)d_in[4];
    float*        out    = (float*)d_out;

    (void)in_sizes; (void)n_in; (void)out_size;

    // 1) fp32 -> fp16: feature table + W transpose
    convert_kernel<<<FEATS_BLOCKS + W_BLOCKS, 256>>>(feats4, W);

    // 2) gather+mean (even bids) interleaved with x_self convert (odd bids)
    gather_xself_kernel<<<NGATHER + XSELF_BLOCKS, 256>>>(nidx, xself4);

    // 3) fp16 tensor-core GEMM (grid: x = n-tiles, y = m-tiles)
    dim3 grid(NOUT / BN, (BATCH + BM - 1) / BM);
    gemm_f16_pipe_kernel<<<grid, 256>>>(bias, out, BATCH);
}

// round 13
// speedup vs baseline: 1.0124x; 1.0124x over previous
#include <cuda_runtime.h>
#include <cuda_fp16.h>
#include <cstdint>

// Problem constants (fixed by the reference)
#define BATCH   50000
#define KNEI    32
#define FDIM    256     // feature dim; 2F = 512 = GEMM K
#define NNODES  200000
#define NOUT    256

// fp16 copy of the feature table [NNODES, FDIM] (rebuilt every call)
__device__ __half g_feats_h[(size_t)NNODES * FDIM];
// fp16 concatenated GEMM A matrix: [BATCH][512] = [x_self_f16 | x_neigh_f16]
__device__ __half g_h[(size_t)BATCH * 2 * FDIM];
// fp16 transposed weights: W_t[n][k], n in [0,256), k in [0,512)
__device__ __half g_W_t[(size_t)NOUT * 2 * FDIM];

#define FEATS_BLOCKS ((NNODES * FDIM) / (256 * 8))   // 25000
#define XSELF_BLOCKS ((BATCH * FDIM) / (256 * 8))    // 6250
#define W_BLOCKS     ((2 * FDIM / 32) * (NOUT / 32)) // 128

// ---------------------------------------------------------------------------
// Kernel 1: fp32 -> fp16 conversions: feats table, x_self (left half of g_h),
// and W transpose -> W_t.  One streaming launch (HBM-bound, ~53us floor).
// NOTE: do NOT interleave any of this with the gather — both phases bottleneck
// the LTS port, so interleaving gives zero overlap (measured, rounds 9 & 11).
// ---------------------------------------------------------------------------
__global__ void convert_kernel(const float4* __restrict__ feats4,
                               const float4* __restrict__ xself4,
                               const float* __restrict__ W) {
    const int bid = blockIdx.x;
    if (bid < FEATS_BLOCKS) {
        const long long t = (long long)bid * 256 + threadIdx.x;
        const float4 a = feats4[2 * t];
        const float4 b = feats4[2 * t + 1];
        __half2 o[4];
        o[0] = __floats2half2_rn(a.x, a.y);
        o[1] = __floats2half2_rn(a.z, a.w);
        o[2] = __floats2half2_rn(b.x, b.y);
        o[3] = __floats2half2_rn(b.z, b.w);
        *reinterpret_cast<uint4*>(g_feats_h + t * 8) = *reinterpret_cast<uint4*>(o);
    } else if (bid < FEATS_BLOCKS + XSELF_BLOCKS) {
        const long long e = (long long)(bid - FEATS_BLOCKS) * 256 + threadIdx.x;
        const float4 a = xself4[2 * e];
        const float4 b = xself4[2 * e + 1];
        __half2 o[4];
        o[0] = __floats2half2_rn(a.x, a.y);
        o[1] = __floats2half2_rn(a.z, a.w);
        o[2] = __floats2half2_rn(b.x, b.y);
        o[3] = __floats2half2_rn(b.z, b.w);
        const long long row = e / 32;          // 32 * 8 halves = 256 per row
        const long long col = (e % 32) * 8;
        *reinterpret_cast<uint4*>(g_h + row * (2 * FDIM) + col) =
            *reinterpret_cast<uint4*>(o);
    } else {
        // W transpose: 32x32 fp32 tile -> fp16 W_t
        __shared__ float tile[32][33];
        const int b2 = bid - FEATS_BLOCKS - XSELF_BLOCKS;
        const int k0 = (b2 & 15) * 32;      // 16 k-blocks
        const int n0 = (b2 >> 4) * 32;      // 8 n-blocks
        const int tx = threadIdx.x & 31;
        const int ty = threadIdx.x >> 5;    // 0..7
#pragma unroll
        for (int j = 0; j < 4; j++)
            tile[ty + j * 8][tx] = W[(long long)(k0 + ty + j * 8) * NOUT + n0 + tx];
        __syncthreads();
#pragma unroll
        for (int j = 0; j < 4; j++) {
            const int n = ty + j * 8;
            g_W_t[(long long)(n0 + n) * (2 * FDIM) + k0 + tx] =
                __float2half(tile[tx][n]);
        }
    }
}

// ---------------------------------------------------------------------------
// Kernel 2: gather + mean from fp16 table, fp32 accumulate, fp16 out into
// the right half (cols 256..511) of g_h.  8 rows/block, 1 warp per row.
// At the LTS-port floor (~820MB of L2 reads).  Index dtype (int32 vs int64)
// detected per-block: int64 indices < 200000 have all-zero hi words.
// ---------------------------------------------------------------------------
__global__ void gather_mean_kernel(const void* __restrict__ idx_raw) {
    const int tid  = threadIdx.x;
    const int warp = tid >> 5;
    const int lane = tid & 31;

    int hi_zero = 1;
    if (tid < 128) {
        const uint2 probe = reinterpret_cast<const uint2*>(idx_raw)[tid];
        hi_zero = (probe.y == 0u);
    }
    const int is64 = __syncthreads_and(hi_zero);

    __shared__ int sidx[256];
    const long long flat = (long long)blockIdx.x * 256 + tid;
    int v;
    if (is64) v = (int)reinterpret_cast<const long long*>(idx_raw)[flat];
    else      v = reinterpret_cast<const int*>(idx_raw)[flat];
    sidx[tid] = v;
    __syncthreads();

    const int row = blockIdx.x * 8 + warp;

    float acc[8];
#pragma unroll
    for (int j = 0; j < 8; j++) acc[j] = 0.f;

#pragma unroll
    for (int k = 0; k < KNEI; k++) {
        const long long node = sidx[warp * KNEI + k];
        const uint4 raw = *reinterpret_cast<const uint4*>(
            g_feats_h + node * FDIM + lane * 8);
        const __half2* h = reinterpret_cast<const __half2*>(&raw);
#pragma unroll
        for (int j = 0; j < 4; j++) {
            const float2 f = __half22float2(h[j]);
            acc[2 * j]     += f.x;
            acc[2 * j + 1] += f.y;
        }
    }
    const float s = 1.0f / (float)KNEI;
    __half2 o[4];
#pragma unroll
    for (int j = 0; j < 4; j++)
        o[j] = __floats2half2_rn(acc[2 * j] * s, acc[2 * j + 1] * s);
    *reinterpret_cast<uint4*>(g_h + (long long)row * (2 * FDIM) + FDIM + lane * 8) =
        *reinterpret_cast<uint4*>(o);
}

// ---------------------------------------------------------------------------
// Kernel 3: fp16 tensor-core GEMM, 4-stage cp.async pipeline.
//   out[M,256] = g_h[M,512] @ W_t^T + bias
// BM=128, BN=64, BK=32, STAGES=4 (48KB smem, 4 CTAs/SM).  8 warps:
// 4 in M x 2 in N, warp tile 32x32 -> 32 fp32 accs/thread (regs <= 64).
// ONE barrier per stage: the leading __syncthreads at iter u already
// guarantees all warps completed compute(u-1), which is the only condition
// issue(u+3) needs before overwriting buffer (u-1)%4.
// Grid: x = n-tile (4), y = m-tile (391) -> the 4 CTAs sharing an A tile are
// consecutive bids, so A re-reads hit L2 while hot.
// ---------------------------------------------------------------------------
#define BM 128
#define BN 64
#define BK 32
#define STAGES 4
#define A_TILE_B (BM * BK * 2)            // 8192
#define B_TILE_B (BN * BK * 2)            // 4096
#define STAGE_B  (A_TILE_B + B_TILE_B)    // 12288

__device__ __forceinline__ unsigned swz(unsigned off) {
    return off ^ (((off >> 7) & 7u) << 4);
}

__device__ __forceinline__ void mma_f16(float& d0, float& d1, float& d2, float& d3,
                                        unsigned a0, unsigned a1, unsigned a2, unsigned a3,
                                        unsigned b0, unsigned b1) {
    asm volatile(
        "mma.sync.aligned.m16n8k16.row.col.f32.f16.f16.f32 "
        "{%0,%1,%2,%3}, {%4,%5,%6,%7}, {%8,%9}, {%0,%1,%2,%3};"
        : "+f"(d0), "+f"(d1), "+f"(d2), "+f"(d3)
        : "r"(a0), "r"(a1), "r"(a2), "r"(a3), "r"(b0), "r"(b1));
}

__device__ __forceinline__ void ldmatrix_x4(unsigned& r0, unsigned& r1,
                                            unsigned& r2, unsigned& r3,
                                            unsigned saddr) {
    asm volatile("ldmatrix.sync.aligned.m8n8.x4.shared.b16 {%0,%1,%2,%3}, [%4];"
                 : "=r"(r0), "=r"(r1), "=r"(r2), "=r"(r3) : "r"(saddr));
}

__device__ __forceinline__ void cp_async16(unsigned dst, const void* src, int sz) {
    asm volatile("cp.async.cg.shared.global [%0], [%1], 16, %2;\n"
                 :: "r"(dst), "l"(src), "r"(sz));
}
__device__ __forceinline__ void cp_commit() {
    asm volatile("cp.async.commit_group;\n");
}
template <int N>
__device__ __forceinline__ void cp_wait() {
    asm volatile("cp.async.wait_group %0;\n" :: "n"(N));
}

__global__ __launch_bounds__(256, 4)
void gemm_f16_pipe_kernel(const float* __restrict__ bias,
                          float* __restrict__ out,
                          int M) {
    __shared__ __align__(16) char smem[STAGES * STAGE_B];   // 48 KB

    const int bm  = blockIdx.y * BM;
    const int bn  = blockIdx.x * BN;
    const int tid = threadIdx.x;

    const int warp = tid >> 5;
    const int lane = tid & 31;
    const int wm   = warp >> 1;        // 0..3
    const int wn   = warp & 1;         // 0..1
    const int gid  = lane >> 2;        // 0..7
    const int tig  = lane & 3;         // 0..3

    const unsigned sbase = (unsigned)__cvta_generic_to_shared(smem);

    const __half* __restrict__ A  = g_h;
    const __half* __restrict__ Wt = g_W_t;

    // A fragment ldmatrix lane addressing
    const int lm_tile = lane >> 3;
    const int lm_row  = (lane & 7) + (lm_tile & 1) * 8;
    const int lm_koff = (lm_tile >> 1) * 8;
    // B fragment ldmatrix lane addressing (non-trans over [n][k] rows)
    const int bn_row  = ((lane >> 4) & 1) * 8 + (lane & 7);
    const int bk_add  = ((lane >> 3) & 1) * 8;

    float acc[2][4][4];
#pragma unroll
    for (int i = 0; i < 2; i++)
#pragma unroll
        for (int j = 0; j < 4; j++)
#pragma unroll
            for (int q = 0; q < 4; q++) acc[i][j][q] = 0.f;

    // stage s covers k0 = s*BK halves.  Per stage: A = 512 16B-granules
    // (2/thread), B = 256 granules (1/thread).
#define ISSUE_STAGE(s, buf)                                                     \
    {                                                                           \
        const int k0 = (s) * BK;                                                \
        const unsigned abase = sbase + (buf) * STAGE_B;                         \
        const unsigned bbase = abase + A_TILE_B;                                \
        _Pragma("unroll")                                                       \
        for (int i = 0; i < 2; i++) {                                           \
            const int fi = tid + i * 256;                                       \
            const int r  = fi >> 2;                                             \
            const int g  = fi & 3;                                              \
            const unsigned soff = swz((unsigned)(r * 64 + g * 16));             \
            const int m = bm + r;                                               \
            cp_async16(abase + soff,                                            \
                       A + (long long)m * (2 * FDIM) + k0 + g * 8,              \
                       (m < M) ? 16 : 0);                                       \
        }                                                                       \
        {                                                                       \
            const int r = tid >> 2;                                             \
            const int g = tid & 3;                                              \
            const unsigned soff = swz((unsigned)(r * 64 + g * 16));             \
            cp_async16(bbase + soff,                                            \
                       Wt + (long long)(bn + r) * (2 * FDIM) + k0 + g * 8, 16); \
        }                                                                       \
        cp_commit();                                                            \
    }

    // ---- prologue: issue stages 0,1,2 ----
    ISSUE_STAGE(0, 0)
    ISSUE_STAGE(1, 1)
    ISSUE_STAGE(2, 2)

    const int NSTAGE = (2 * FDIM) / BK;   // 16

#pragma unroll 1
    for (int s = 0; s < NSTAGE; s++) {
        if (s < NSTAGE - 2)       cp_wait<2>();
        else if (s == NSTAGE - 2) cp_wait<1>();
        else                      cp_wait<0>();
        // Single barrier per stage: orders (a) everyone's cp_wait for the
        // buffer consumed this stage, and (b) everyone's compute(s-1) before
        // issue(s+3) overwrites buffer (s-1)%4.
        __syncthreads();

        if (s + 3 < NSTAGE) {
            const int nb = (s + 3) % STAGES;
            ISSUE_STAGE(s + 3, nb)
        }

        // compute stage s from buffer s%4
        const unsigned abase = sbase + (s % STAGES) * STAGE_B;
        const unsigned bbase = abase + A_TILE_B;

#pragma unroll
        for (int ks = 0; ks < 2; ks++) {
            const int kk = ks * 16;
            unsigned af[2][4];
#pragma unroll
            for (int mi = 0; mi < 2; mi++) {
                const int r = wm * 32 + mi * 16 + lm_row;
                const unsigned sa = abase + swz((unsigned)(r * 64 + (kk + lm_koff) * 2));
                ldmatrix_x4(af[mi][0], af[mi][1], af[mi][2], af[mi][3], sa);
            }
            unsigned bf[4][2];
#pragma unroll
            for (int nj2 = 0; nj2 < 2; nj2++) {
                const int n = wn * 32 + nj2 * 16 + bn_row;
                const unsigned sb = bbase + swz((unsigned)(n * 64 + (kk + bk_add) * 2));
                unsigned r0, r1, r2, r3;
                ldmatrix_x4(r0, r1, r2, r3, sb);
                bf[2 * nj2][0]     = r0; bf[2 * nj2][1]     = r1;
                bf[2 * nj2 + 1][0] = r2; bf[2 * nj2 + 1][1] = r3;
            }
#pragma unroll
            for (int nj = 0; nj < 4; nj++) {
                mma_f16(acc[0][nj][0], acc[0][nj][1], acc[0][nj][2], acc[0][nj][3],
                        af[0][0], af[0][1], af[0][2], af[0][3], bf[nj][0], bf[nj][1]);
                mma_f16(acc[1][nj][0], acc[1][nj][1], acc[1][nj][2], acc[1][nj][3],
                        af[1][0], af[1][1], af[1][2], af[1][3], bf[nj][0], bf[nj][1]);
            }
        }
        // no trailing barrier: next iteration's leading barrier provides the
        // required ordering before any buffer reuse.
    }

    // ---- epilogue: bias + store (c0,c1 contiguous -> float2) ----
#pragma unroll
    for (int mi = 0; mi < 2; mi++) {
        const int m0 = bm + wm * 32 + mi * 16 + gid;
#pragma unroll
        for (int nj = 0; nj < 4; nj++) {
            const int n = bn + wn * 32 + nj * 8 + 2 * tig;
            const float b0 = bias[n];
            const float b1 = bias[n + 1];
            if (m0 < M) {
                float2 v = make_float2(acc[mi][nj][0] + b0, acc[mi][nj][1] + b1);
                *reinterpret_cast<float2*>(out + (long long)m0 * NOUT + n) = v;
            }
            if (m0 + 8 < M) {
                float2 v = make_float2(acc[mi][nj][2] + b0, acc[mi][nj][3] + b1);
                *reinterpret_cast<float2*>(out + (long long)(m0 + 8) * NOUT + n) = v;
            }
        }
    }
#undef ISSUE_STAGE
}

// ---------------------------------------------------------------------------
// Launch
// Inputs: x_self[f32 B*F], feats[f32 N*F], neigh_idx[B*K], W[f32 512*256], b[f32 256]
// ---------------------------------------------------------------------------
extern "C" void kernel_launch(void* const* d_in, const int* in_sizes, int n_in,
                              void* d_out, int out_size) {
    const float4* xself4 = (const float4*)d_in[0];
    const float4* feats4 = (const float4*)d_in[1];
    const void*   nidx   = d_in[2];
    const float*  W      = (const float*)d_in[3];
    const float*  bias   = (const float*)d_in[4];
    float*        out    = (float*)d_out;

    (void)in_sizes; (void)n_in; (void)out_size;

    // 1) fp32 -> fp16: feature table, x_self, W transpose (one launch)
    convert_kernel<<<FEATS_BLOCKS + XSELF_BLOCKS + W_BLOCKS, 256>>>(
        feats4, xself4, W);

    // 2) gather + mean -> right half of g_h
    gather_mean_kernel<<<BATCH / 8, 256>>>(nidx);

    // 3) fp16 tensor-core GEMM (grid: x = n-tiles, y = m-tiles)
    dim3 grid(NOUT / BN, (BATCH + BM - 1) / BM);
    gemm_f16_pipe_kernel<<<grid, 256>>>(bias, out, BATCH);
}

// round 14
// speedup vs baseline: 1.0170x; 1.0046x over previous
#include <cuda_runtime.h>
#include <cuda_fp16.h>
#include <cstdint>

// Problem constants (fixed by the reference)
#define BATCH   50000
#define KNEI    32
#define FDIM    256     // feature dim; 2F = 512 = GEMM K
#define NNODES  200000
#define NOUT    256

// fp16 copy of the feature table [NNODES, FDIM] (rebuilt every call)
__device__ __half g_feats_h[(size_t)NNODES * FDIM];
// fp16 concatenated GEMM A matrix: [BATCH][512] = [x_self_f16 | x_neigh_f16]
__device__ __half g_h[(size_t)BATCH * 2 * FDIM];
// fp16 transposed weights: W_t[n][k], n in [0,256), k in [0,512)
__device__ __half g_W_t[(size_t)NOUT * 2 * FDIM];

#define FEATS_BLOCKS ((NNODES * FDIM) / (256 * 8))   // 25000
#define XSELF_BLOCKS ((BATCH * FDIM) / (256 * 8))    // 6250
#define W_BLOCKS     ((2 * FDIM / 32) * (NOUT / 32)) // 128

// ---------------------------------------------------------------------------
// Kernel 1: fp32 -> fp16 conversions: feats table, x_self (left half of g_h),
// and W transpose -> W_t.  One streaming launch (HBM-bound floor ~53us).
// NOTE: do NOT interleave any of this with the gather — both phases bottleneck
// the LTS port, so interleaving gives zero overlap (measured, rounds 9 & 11).
// ---------------------------------------------------------------------------
__global__ void convert_kernel(const float4* __restrict__ feats4,
                               const float4* __restrict__ xself4,
                               const float* __restrict__ W) {
    const int bid = blockIdx.x;
    if (bid < FEATS_BLOCKS) {
        const long long t = (long long)bid * 256 + threadIdx.x;
        const float4 a = feats4[2 * t];
        const float4 b = feats4[2 * t + 1];
        __half2 o[4];
        o[0] = __floats2half2_rn(a.x, a.y);
        o[1] = __floats2half2_rn(a.z, a.w);
        o[2] = __floats2half2_rn(b.x, b.y);
        o[3] = __floats2half2_rn(b.z, b.w);
        *reinterpret_cast<uint4*>(g_feats_h + t * 8) = *reinterpret_cast<uint4*>(o);
    } else if (bid < FEATS_BLOCKS + XSELF_BLOCKS) {
        const long long e = (long long)(bid - FEATS_BLOCKS) * 256 + threadIdx.x;
        const float4 a = xself4[2 * e];
        const float4 b = xself4[2 * e + 1];
        __half2 o[4];
        o[0] = __floats2half2_rn(a.x, a.y);
        o[1] = __floats2half2_rn(a.z, a.w);
        o[2] = __floats2half2_rn(b.x, b.y);
        o[3] = __floats2half2_rn(b.z, b.w);
        const long long row = e / 32;          // 32 * 8 halves = 256 per row
        const long long col = (e % 32) * 8;
        *reinterpret_cast<uint4*>(g_h + row * (2 * FDIM) + col) =
            *reinterpret_cast<uint4*>(o);
    } else {
        // W transpose: 32x32 fp32 tile -> fp16 W_t
        __shared__ float tile[32][33];
        const int b2 = bid - FEATS_BLOCKS - XSELF_BLOCKS;
        const int k0 = (b2 & 15) * 32;      // 16 k-blocks
        const int n0 = (b2 >> 4) * 32;      // 8 n-blocks
        const int tx = threadIdx.x & 31;
        const int ty = threadIdx.x >> 5;    // 0..7
#pragma unroll
        for (int j = 0; j < 4; j++)
            tile[ty + j * 8][tx] = W[(long long)(k0 + ty + j * 8) * NOUT + n0 + tx];
        __syncthreads();
#pragma unroll
        for (int j = 0; j < 4; j++) {
            const int n = ty + j * 8;
            g_W_t[(long long)(n0 + n) * (2 * FDIM) + k0 + tx] =
                __float2half(tile[tx][n]);
        }
    }
}

// ---------------------------------------------------------------------------
// Kernel 2: gather + mean from fp16 table, fp32 accumulate, fp16 out into
// the right half (cols 256..511) of g_h.  8 rows/block, 1 warp per row.
// At the LTS-port floor (~820MB of L2 reads).  Index dtype (int32 vs int64)
// detected per-block: int64 indices < 200000 have all-zero hi words.
// ---------------------------------------------------------------------------
__global__ void gather_mean_kernel(const void* __restrict__ idx_raw) {
    const int tid  = threadIdx.x;
    const int warp = tid >> 5;
    const int lane = tid & 31;

    int hi_zero = 1;
    if (tid < 128) {
        const uint2 probe = reinterpret_cast<const uint2*>(idx_raw)[tid];
        hi_zero = (probe.y == 0u);
    }
    const int is64 = __syncthreads_and(hi_zero);

    __shared__ int sidx[256];
    const long long flat = (long long)blockIdx.x * 256 + tid;
    int v;
    if (is64) v = (int)reinterpret_cast<const long long*>(idx_raw)[flat];
    else      v = reinterpret_cast<const int*>(idx_raw)[flat];
    sidx[tid] = v;
    __syncthreads();

    const int row = blockIdx.x * 8 + warp;

    float acc[8];
#pragma unroll
    for (int j = 0; j < 8; j++) acc[j] = 0.f;

#pragma unroll
    for (int k = 0; k < KNEI; k++) {
        const long long node = sidx[warp * KNEI + k];
        const uint4 raw = *reinterpret_cast<const uint4*>(
            g_feats_h + node * FDIM + lane * 8);
        const __half2* h = reinterpret_cast<const __half2*>(&raw);
#pragma unroll
        for (int j = 0; j < 4; j++) {
            const float2 f = __half22float2(h[j]);
            acc[2 * j]     += f.x;
            acc[2 * j + 1] += f.y;
        }
    }
    const float s = 1.0f / (float)KNEI;
    __half2 o[4];
#pragma unroll
    for (int j = 0; j < 4; j++)
        o[j] = __floats2half2_rn(acc[2 * j] * s, acc[2 * j + 1] * s);
    *reinterpret_cast<uint4*>(g_h + (long long)row * (2 * FDIM) + FDIM + lane * 8) =
        *reinterpret_cast<uint4*>(o);
}

// ---------------------------------------------------------------------------
// Kernel 3: fp16 tensor-core GEMM, 4-stage cp.async pipeline.
//   out[M,256] = g_h[M,512] @ W_t^T + bias
// BM=128, BN=64, BK=32, STAGES=4 (48KB smem, 4 CTAs/SM).  8 warps:
// 4 in M x 2 in N, warp tile 32x32 -> 32 fp32 accs/thread (regs <= 64).
// ONE barrier per stage (leading sync covers buffer-reuse ordering).
// Stage loop FULLY UNROLLED: swizzled smem offsets / wait counts become
// immediates; gmem pointers strength-reduced (advance by BK per stage).
// Grid: x = n-tile (4), y = m-tile (391) -> the 4 CTAs sharing an A tile are
// consecutive bids, so A re-reads hit L2 while hot.
// ---------------------------------------------------------------------------
#define BM 128
#define BN 64
#define BK 32
#define STAGES 4
#define A_TILE_B (BM * BK * 2)            // 8192
#define B_TILE_B (BN * BK * 2)            // 4096
#define STAGE_B  (A_TILE_B + B_TILE_B)    // 12288

__device__ __forceinline__ unsigned swz(unsigned off) {
    return off ^ (((off >> 7) & 7u) << 4);
}

__device__ __forceinline__ void mma_f16(float& d0, float& d1, float& d2, float& d3,
                                        unsigned a0, unsigned a1, unsigned a2, unsigned a3,
                                        unsigned b0, unsigned b1) {
    asm volatile(
        "mma.sync.aligned.m16n8k16.row.col.f32.f16.f16.f32 "
        "{%0,%1,%2,%3}, {%4,%5,%6,%7}, {%8,%9}, {%0,%1,%2,%3};"
        : "+f"(d0), "+f"(d1), "+f"(d2), "+f"(d3)
        : "r"(a0), "r"(a1), "r"(a2), "r"(a3), "r"(b0), "r"(b1));
}

__device__ __forceinline__ void ldmatrix_x4(unsigned& r0, unsigned& r1,
                                            unsigned& r2, unsigned& r3,
                                            unsigned saddr) {
    asm volatile("ldmatrix.sync.aligned.m8n8.x4.shared.b16 {%0,%1,%2,%3}, [%4];"
                 : "=r"(r0), "=r"(r1), "=r"(r2), "=r"(r3) : "r"(saddr));
}

__device__ __forceinline__ void cp_async16(unsigned dst, const void* src, int sz) {
    asm volatile("cp.async.cg.shared.global [%0], [%1], 16, %2;\n"
                 :: "r"(dst), "l"(src), "r"(sz));
}
__device__ __forceinline__ void cp_commit() {
    asm volatile("cp.async.commit_group;\n");
}
template <int N>
__device__ __forceinline__ void cp_wait() {
    asm volatile("cp.async.wait_group %0;\n" :: "n"(N));
}

__global__ __launch_bounds__(256, 4)
void gemm_f16_pipe_kernel(const float* __restrict__ bias,
                          float* __restrict__ out,
                          int M) {
    __shared__ __align__(16) char smem[STAGES * STAGE_B];   // 48 KB

    const int bm  = blockIdx.y * BM;
    const int bn  = blockIdx.x * BN;
    const int tid = threadIdx.x;

    const int warp = tid >> 5;
    const int lane = tid & 31;
    const int wm   = warp >> 1;        // 0..3
    const int wn   = warp & 1;         // 0..1
    const int gid  = lane >> 2;        // 0..7
    const int tig  = lane & 3;         // 0..3

    const unsigned sbase = (unsigned)__cvta_generic_to_shared(smem);

    // ---- stage-invariant cp.async mapping (hoisted) ----
    // A granule 0: row tid>>2, gcol tid&3 ; A granule 1: row 64 + (tid>>2)
    // B granule  : row tid>>2, gcol tid&3
    const int gr  = tid >> 2;          // 0..63
    const int gg  = tid & 3;           // 0..3
    const unsigned soffA0 = swz((unsigned)(gr * 64 + gg * 16));
    const unsigned soffA1 = swz((unsigned)((gr + 64) * 64 + gg * 16));
    const unsigned soffB  = soffA0;
    const int mA0 = bm + gr;
    const int mA1 = bm + gr + 64;
    const int szA0 = (mA0 < M) ? 16 : 0;
    const int szA1 = (mA1 < M) ? 16 : 0;
    // source pointers at stage 0 (advance BK halves per stage)
    const __half* pA0 = g_h  + (long long)mA0 * (2 * FDIM) + gg * 8;
    const __half* pA1 = g_h  + (long long)mA1 * (2 * FDIM) + gg * 8;
    const __half* pB  = g_W_t + (long long)(bn + gr) * (2 * FDIM) + gg * 8;

    // A fragment ldmatrix lane addressing
    const int lm_tile = lane >> 3;
    const int lm_row  = (lane & 7) + (lm_tile & 1) * 8;
    const int lm_koff = (lm_tile >> 1) * 8;
    // B fragment ldmatrix lane addressing (non-trans over [n][k] rows)
    const int bn_row  = ((lane >> 4) & 1) * 8 + (lane & 7);
    const int bk_add  = ((lane >> 3) & 1) * 8;

    float acc[2][4][4];
#pragma unroll
    for (int i = 0; i < 2; i++)
#pragma unroll
        for (int j = 0; j < 4; j++)
#pragma unroll
            for (int q = 0; q < 4; q++) acc[i][j][q] = 0.f;

#define ISSUE_STAGE(s, buf)                                                     \
    {                                                                           \
        const unsigned abase = sbase + (buf) * STAGE_B;                         \
        cp_async16(abase + soffA0, pA0 + (s) * BK, szA0);                       \
        cp_async16(abase + soffA1, pA1 + (s) * BK, szA1);                       \
        cp_async16(abase + A_TILE_B + soffB, pB + (s) * BK, 16);                \
        cp_commit();                                                            \
    }

    // ---- prologue: issue stages 0,1,2 ----
    ISSUE_STAGE(0, 0)
    ISSUE_STAGE(1, 1)
    ISSUE_STAGE(2, 2)

    const int NSTAGE = (2 * FDIM) / BK;   // 16

#pragma unroll
    for (int s = 0; s < NSTAGE; s++) {
        if (s < NSTAGE - 2)       cp_wait<2>();
        else if (s == NSTAGE - 2) cp_wait<1>();
        else                      cp_wait<0>();
        // Single barrier per stage: orders (a) everyone's cp_wait for the
        // buffer consumed this stage, and (b) everyone's compute(s-1) before
        // issue(s+3) overwrites buffer (s-1)%4.
        __syncthreads();

        if (s + 3 < NSTAGE) {
            ISSUE_STAGE(s + 3, (s + 3) % STAGES)
        }

        // compute stage s from buffer s%4
        const unsigned abase = sbase + (s % STAGES) * STAGE_B;
        const unsigned bbase = abase + A_TILE_B;

#pragma unroll
        for (int ks = 0; ks < 2; ks++) {
            const int kk = ks * 16;
            unsigned af[2][4];
#pragma unroll
            for (int mi = 0; mi < 2; mi++) {
                const int r = wm * 32 + mi * 16 + lm_row;
                const unsigned sa = abase + swz((unsigned)(r * 64 + (kk + lm_koff) * 2));
                ldmatrix_x4(af[mi][0], af[mi][1], af[mi][2], af[mi][3], sa);
            }
            unsigned bf[4][2];
#pragma unroll
            for (int nj2 = 0; nj2 < 2; nj2++) {
                const int n = wn * 32 + nj2 * 16 + bn_row;
                const unsigned sb = bbase + swz((unsigned)(n * 64 + (kk + bk_add) * 2));
                unsigned r0, r1, r2, r3;
                ldmatrix_x4(r0, r1, r2, r3, sb);
                bf[2 * nj2][0]     = r0; bf[2 * nj2][1]     = r1;
                bf[2 * nj2 + 1][0] = r2; bf[2 * nj2 + 1][1] = r3;
            }
#pragma unroll
            for (int nj = 0; nj < 4; nj++) {
                mma_f16(acc[0][nj][0], acc[0][nj][1], acc[0][nj][2], acc[0][nj][3],
                        af[0][0], af[0][1], af[0][2], af[0][3], bf[nj][0], bf[nj][1]);
                mma_f16(acc[1][nj][0], acc[1][nj][1], acc[1][nj][2], acc[1][nj][3],
                        af[1][0], af[1][1], af[1][2], af[1][3], bf[nj][0], bf[nj][1]);
            }
        }
        // no trailing barrier: next iteration's leading barrier provides the
        // required ordering before any buffer reuse.
    }

    // ---- epilogue: bias + store (c0,c1 contiguous -> float2) ----
#pragma unroll
    for (int mi = 0; mi < 2; mi++) {
        const int m0 = bm + wm * 32 + mi * 16 + gid;
#pragma unroll
        for (int nj = 0; nj < 4; nj++) {
            const int n = bn + wn * 32 + nj * 8 + 2 * tig;
            const float b0 = bias[n];
            const float b1 = bias[n + 1];
            if (m0 < M) {
                float2 v = make_float2(acc[mi][nj][0] + b0, acc[mi][nj][1] + b1);
                *reinterpret_cast<float2*>(out + (long long)m0 * NOUT + n) = v;
            }
            if (m0 + 8 < M) {
                float2 v = make_float2(acc[mi][nj][2] + b0, acc[mi][nj][3] + b1);
                *reinterpret_cast<float2*>(out + (long long)(m0 + 8) * NOUT + n) = v;
            }
        }
    }
#undef ISSUE_STAGE
}

// ---------------------------------------------------------------------------
// Launch
// Inputs: x_self[f32 B*F], feats[f32 N*F], neigh_idx[B*K], W[f32 512*256], b[f32 256]
// ---------------------------------------------------------------------------
extern "C" void kernel_launch(void* const* d_in, const int* in_sizes, int n_in,
                              void* d_out, int out_size) {
    const float4* xself4 = (const float4*)d_in[0];
    const float4* feats4 = (const float4*)d_in[1];
    const void*   nidx   = d_in[2];
    const float*  W      = (const float*)d_in[3];
    const float*  bias   = (const float*)d_in[4];
    float*        out    = (float*)d_out;

    (void)in_sizes; (void)n_in; (void)out_size;

    // 1) fp32 -> fp16: feature table, x_self, W transpose (one launch)
    convert_kernel<<<FEATS_BLOCKS + XSELF_BLOCKS + W_BLOCKS, 256>>>(
        feats4, xself4, W);

    // 2) gather + mean -> right half of g_h
    gather_mean_kernel<<<BATCH / 8, 256>>>(nidx);

    // 3) fp16 tensor-core GEMM (grid: x = n-tiles, y = m-tiles)
    dim3 grid(NOUT / BN, (BATCH + BM - 1) / BM);
    gemm_f16_pipe_kernel<<<grid, 256>>>(bias, out, BATCH);
}